// round 8
// baseline (speedup 1.0000x reference)
#include <cuda_runtime.h>

// Problem constants (fixed by the dataset)
#define BB 16
#define TT 128
#define UU 64
#define VV 1024
#define CELLS (BB * TT * UU)      // 131072
#define NEGF   (-1e30f)
#define LOG2EF 1.4426950408889634f
#define LN2F   0.6931471805599453f

// Scratch (allocation-free rule: __device__ globals)
// lp tables stored PRE-SCALED by log2(e) (log2-domain DP).
__device__ float g_lpb[CELLS];    // lp_blank * log2e
__device__ float g_lpl[CELLS];    // lp_label * log2e (u < UU-1 valid)
__device__ float g_cost[BB];
__device__ int   g_ticket;        // last-block-done counter (zero-init; winner resets)

// ---------------------------------------------------------------------------
// FFMA-only expf (phase-1 bulk): avoids MUFU throughput wall at 134M ops.
// ---------------------------------------------------------------------------
__device__ __forceinline__ float fexp(float x) {
    const float C1    = 1.4426950408889634f;
    const float MAGIC = 12582912.0f;           // 1.5 * 2^23
    float z = fmaf(x, C1, MAGIC);
    float d = MAGIC - z;
    float f = fmaf(x, C1, d);
    float p = fmaf(f, 0.0096181291076285f, 0.0555041086648216f);
    p = fmaf(f, p, 0.2402265069591007f);
    p = fmaf(f, p, 0.6931471805599453f);
    p = fmaf(f, p, 1.0f);
    return __int_as_float(__float_as_int(p) + (__float_as_int(z) << 23));
}

__device__ __forceinline__ float fast_ex2(float x) {
    float r; asm("ex2.approx.ftz.f32 %0, %1;" : "=f"(r) : "f"(x)); return r;
}
__device__ __forceinline__ float fast_lg2(float x) {
    float r; asm("lg2.approx.ftz.f32 %0, %1;" : "=f"(r) : "f"(x)); return r;
}

// ---------------------------------------------------------------------------
// Phase 1: one warp per (b,t,u) cell; 8 front-batched float4 streaming loads.
// At 86.6% DRAM — the streaming floor; unchanged.
// ---------------------------------------------------------------------------
__global__ void __launch_bounds__(256) lse_kernel(const float* __restrict__ acts,
                                                  const int*   __restrict__ labels) {
    int warp = blockIdx.x * 8 + (threadIdx.x >> 5);
    int lane = threadIdx.x & 31;
    const float*  base = acts + (size_t)warp * VV;
    const float4* p4   = (const float4*)base;

    float4 v[8];
#pragma unroll
    for (int i = 0; i < 8; i++)
        v[i] = __ldcs(&p4[i * 32 + lane]);

    float blank = v[0].x;                      // valid on lane 0 only
    float s0 = 0.f, s1 = 0.f, s2 = 0.f, s3 = 0.f;
#pragma unroll
    for (int i = 0; i < 8; i++) {
        s0 += fexp(v[i].x);
        s1 += fexp(v[i].y);
        s2 += fexp(v[i].z);
        s3 += fexp(v[i].w);
    }
    float s = (s0 + s1) + (s2 + s3);
#pragma unroll
    for (int o = 16; o; o >>= 1)
        s += __shfl_xor_sync(0xffffffffu, s, o);

    float lse2 = fast_lg2(s);                  // log2-domain lse

    if (lane == 0) {
        g_lpb[warp] = fmaf(blank, LOG2EF, -lse2);
        int u = warp & (UU - 1);
        if (u < UU - 1) {
            int b   = warp >> 13;
            int lab = labels[b * (UU - 1) + u];
            g_lpl[warp] = fmaf(base[lab], LOG2EF, -lse2);
        }
    }
}

// ---------------------------------------------------------------------------
// Phase 2+3: 2-diagonal-fused DP (95 super-steps), one warp/batch, 2 cells
// per lane. Serial warp is alone on its SMSP -> MUFU issue (rt 8/SMSP) is
// the binding rate. This round:
//  * MEDIAN TRICK: one LAE3 source is always the max (ex2(0)=1), and the
//    two non-max values are branch-free: o1=min(x,y), o2=min(max(x,y),z).
//    e = 1 + ex2(o1-M) + ex2(o2-M) -> 3 MUFU/cell instead of 4.
//  * NO lp staging: weight build reads g_lpb/g_lpl straight from L2.
//  * freeze folded into weights (exact identity), float4 weights with
//    one-step register prefetch, final-step shfls peeled.
// smem: weights only, (6144+128) float4 = 100352 B.
// ---------------------------------------------------------------------------
__global__ void __launch_bounds__(256) dp_kernel(float* __restrict__ out) {
    int b = blockIdx.x;
    extern __shared__ float sm[];
    float4* wq = (float4*)sm;           // 6144 + 128 pad entries
    int tid = threadIdx.x;

    const float* __restrict__ gb = g_lpb + b * TT * UU;
    const float* __restrict__ gl = g_lpl + b * TT * UU;

    // Build fused weights for s in [1,95], u in [0,63]: j = s*64 + u.
    // Reads hit L2 (tables written by lse_kernel, 1 MB total).
#pragma unroll 4
    for (int j = 64 + tid; j < 6144; j += 256) {
        int s = j >> 6, u = j & 63;
        int t = 2 * s - u;
        int r0 = min(max(t,     0), TT - 1);
        int r1 = min(max(t - 1, 0), TT - 1);
        int r2 = min(max(t - 2, 0), TT - 1);
        int um1 = max(u - 1, 0);
        int um2 = max(u - 2, 0);

        float b_r1u   = __ldg(&gb[r1 * UU + u]);
        float b_r2u   = __ldg(&gb[r2 * UU + u]);
        float l_r0um1 = __ldg(&gl[r0 * UU + um1]);
        float l_r1um1 = __ldg(&gl[r1 * UU + um1]);
        float b_r1um1 = __ldg(&gb[r1 * UU + um1]);
        float l_r0um2 = __ldg(&gl[r0 * UU + um2]);

        float A  = b_r2u + b_r1u;
        float B1 = l_r1um1 + b_r1u;                  // label@(t-1) then blank
        float B2 = b_r1um1 + l_r0um1;                // blank@(t-1) then label
        float MBv = fmaxf(B1, B2);
        float B  = MBv + fast_lg2(fast_ex2(B1 - MBv) + fast_ex2(B2 - MBv));
        float C  = l_r0um2 + l_r0um1;
        if (u == 0) B = NEGF;
        if (u < 2)  C = NEGF;
        if (t > TT - 1) { A = 0.f; B = NEGF; C = NEGF; }   // exact freeze
        wq[j] = make_float4(A, B, C, 0.f);
    }
    // pad region (prefetch overrun at s=95 reads the s=96 row)
    if (tid < 128) wq[6144 + tid] = make_float4(0.f, NEGF, NEGF, 0.f);
    __syncthreads();
    if (tid >= 32) return;              // warp 0 runs the serial DP

    int lane = tid;
    int u_lo = lane * 2;

    // s=0 state: only alpha[0,0] = 0 live.
    float a_lo = (lane == 0) ? 0.f : NEGF;
    float a_hi = NEGF;
    float nl_lo = __shfl_up_sync(0xffffffffu, a_lo, 1);
    float nl_hi = __shfl_up_sync(0xffffffffu, a_hi, 1);

    int W = 64 + u_lo;
    float4 w0 = wq[W], w1 = wq[W + 1];

#pragma unroll 2
    for (int s = 1; s <= 94; s++) {
        float4 nw0 = wq[W + 64];        // prefetch next step's weights
        float4 nw1 = wq[W + 65];

        float x0 = a_lo  + w0.x;
        float y0 = nl_hi + w0.y;
        float z0 = nl_lo + w0.z;
        float x1 = a_hi  + w1.x;
        float y1 = a_lo  + w1.y;        // pre-update a_lo (s-1 value)
        float z1 = nl_hi + w1.z;

        // median trick: M = max3; o1,o2 = the two non-max values
        float lo0 = fminf(x0, y0), hi0 = fmaxf(x0, y0);
        float M0  = fmaxf(hi0, z0);
        float e0  = 1.0f + fast_ex2(lo0 - M0) + fast_ex2(fminf(hi0, z0) - M0);
        a_lo = M0 + fast_lg2(e0);

        float lo1 = fminf(x1, y1), hi1 = fmaxf(x1, y1);
        float M1  = fmaxf(hi1, z1);
        float e1  = 1.0f + fast_ex2(lo1 - M1) + fast_ex2(fminf(hi1, z1) - M1);
        a_hi = M1 + fast_lg2(e1);

        nl_lo = __shfl_up_sync(0xffffffffu, a_lo, 1);
        nl_hi = __shfl_up_sync(0xffffffffu, a_hi, 1);

        w0 = nw0; w1 = nw1; W += 64;
    }
    // s = 95 peeled: no trailing shfls, only a_hi needed.
    {
        float x1 = a_hi  + w1.x;
        float y1 = a_lo  + w1.y;
        float z1 = nl_hi + w1.z;
        float lo1 = fminf(x1, y1), hi1 = fmaxf(x1, y1);
        float M1  = fmaxf(hi1, z1);
        float e1  = 1.0f + fast_ex2(lo1 - M1) + fast_ex2(fminf(hi1, z1) - M1);
        a_hi = M1 + fast_lg2(e1);
    }

    // lane 31 a_hi = alpha[T-1, U-1]; add final blank, back to nat domain.
    int is_last = 0;
    if (lane == 31) {
        g_cost[b] = -(a_hi + __ldg(&gb[(TT - 1) * UU + (UU - 1)])) * LN2F;
        __threadfence();
        is_last = (atomicAdd(&g_ticket, 1) == BB - 1);
    }
    is_last = __shfl_sync(0xffffffffu, is_last, 31);

    if (is_last) {
        float v = (lane < BB) ? __ldcg(&g_cost[lane]) : 0.f;
#pragma unroll
        for (int o = 16; o; o >>= 1)
            v += __shfl_xor_sync(0xffffffffu, v, o);
        if (lane == 0) {
            out[0] = v * (1.0f / BB);
            g_ticket = 0;                // reset for next graph replay
        }
    }
}

extern "C" void kernel_launch(void* const* d_in, const int* in_sizes, int n_in,
                              void* d_out, int out_size) {
    const float* acts   = (const float*)d_in[0];
    const int*   labels = (const int*)d_in[1];

    const int smem_bytes = (6144 + 128) * 16;   // 100352 B of float4 weights
    cudaFuncSetAttribute(dp_kernel, cudaFuncAttributeMaxDynamicSharedMemorySize,
                         smem_bytes);

    lse_kernel<<<CELLS / 8, 256>>>(acts, labels);
    dp_kernel<<<BB, 256, smem_bytes>>>((float*)d_out);
}

// round 9
// speedup vs baseline: 1.0560x; 1.0560x over previous
#include <cuda_runtime.h>

// Problem constants (fixed by the dataset)
#define BB 16
#define TT 128
#define UU 64
#define VV 1024
#define CELLS (BB * TT * UU)      // 131072
#define NEGF   (-1e30f)
#define LOG2EF 1.4426950408889634f
#define LN2F   0.6931471805599453f

// Scratch (allocation-free rule: __device__ globals)
// lp tables stored PRE-SCALED by log2(e) (log2-domain DP).
__device__ float g_lpb[CELLS];    // lp_blank * log2e
__device__ float g_lpl[CELLS];    // lp_label * log2e (u < UU-1 valid; col 63 never written)
__device__ float g_cost[BB];
__device__ int   g_ticket;        // last-block-done counter (zero-init; winner resets)

// ---------------------------------------------------------------------------
// FFMA-only expf (phase-1 bulk): avoids MUFU throughput wall at 134M ops.
// ---------------------------------------------------------------------------
__device__ __forceinline__ float fexp(float x) {
    const float C1    = 1.4426950408889634f;
    const float MAGIC = 12582912.0f;           // 1.5 * 2^23
    float z = fmaf(x, C1, MAGIC);
    float d = MAGIC - z;
    float f = fmaf(x, C1, d);
    float p = fmaf(f, 0.0096181291076285f, 0.0555041086648216f);
    p = fmaf(f, p, 0.2402265069591007f);
    p = fmaf(f, p, 0.6931471805599453f);
    p = fmaf(f, p, 1.0f);
    return __int_as_float(__float_as_int(p) + (__float_as_int(z) << 23));
}

__device__ __forceinline__ float fast_ex2(float x) {
    float r; asm("ex2.approx.ftz.f32 %0, %1;" : "=f"(r) : "f"(x)); return r;
}
__device__ __forceinline__ float fast_lg2(float x) {
    float r; asm("lg2.approx.ftz.f32 %0, %1;" : "=f"(r) : "f"(x)); return r;
}
__device__ __forceinline__ float lae2(float a, float b) {
    float M = fmaxf(a, b);
    return M + fast_lg2(fast_ex2(a - M) + fast_ex2(b - M));
}
// LAE3 with median trick: the max term contributes ex2(0)=1 exactly.
__device__ __forceinline__ float lae3(float x, float y, float z) {
    float lo = fminf(x, y), hi = fmaxf(x, y);
    float M  = fmaxf(hi, z);
    float e  = 1.0f + fast_ex2(lo - M) + fast_ex2(fminf(hi, z) - M);
    return M + fast_lg2(e);
}

// ---------------------------------------------------------------------------
// Phase 1: one warp per (b,t,u) cell; 8 front-batched float4 streaming loads.
// At 86.6% DRAM — the streaming floor; unchanged.
// ---------------------------------------------------------------------------
__global__ void __launch_bounds__(256) lse_kernel(const float* __restrict__ acts,
                                                  const int*   __restrict__ labels) {
    int warp = blockIdx.x * 8 + (threadIdx.x >> 5);
    int lane = threadIdx.x & 31;
    const float*  base = acts + (size_t)warp * VV;
    const float4* p4   = (const float4*)base;

    float4 v[8];
#pragma unroll
    for (int i = 0; i < 8; i++)
        v[i] = __ldcs(&p4[i * 32 + lane]);

    float blank = v[0].x;                      // valid on lane 0 only
    float s0 = 0.f, s1 = 0.f, s2 = 0.f, s3 = 0.f;
#pragma unroll
    for (int i = 0; i < 8; i++) {
        s0 += fexp(v[i].x);
        s1 += fexp(v[i].y);
        s2 += fexp(v[i].z);
        s3 += fexp(v[i].w);
    }
    float s = (s0 + s1) + (s2 + s3);
#pragma unroll
    for (int o = 16; o; o >>= 1)
        s += __shfl_xor_sync(0xffffffffu, s, o);

    float lse2 = fast_lg2(s);                  // log2-domain lse

    if (lane == 0) {
        g_lpb[warp] = fmaf(blank, LOG2EF, -lse2);
        int u = warp & (UU - 1);
        if (u < UU - 1) {
            int b   = warp >> 13;
            int lab = labels[b * (UU - 1) + u];
            g_lpl[warp] = fmaf(base[lab], LOG2EF, -lse2);
        }
    }
}

// ---------------------------------------------------------------------------
// Phase 2+3: BIDIRECTIONAL 2-diagonal-fused DP, one block per batch.
//  warp 0: forward alpha, 48 super-steps, diag 0 -> 96 (t <= 96: NO freeze)
//  warp 1: backward beta, 47 super-steps, diag 190 -> 96
//  meet:   loglike = LAE_u(alpha[96-u,u] + beta[96-u,u])   (every path
//          crosses diag 96 exactly once; beta includes the cell's emission)
// Serial depth 95 -> 48. Weights precomputed by all 256 threads from
// smem-staged lp tables (R8 lesson: L2-direct build regressed). Median
// trick: 2 ex2 per LAE3. NEG sentinels absorb all out-of-lattice sources
// exactly (values stay finite; ex2 underflows to exact 0).
// smem floats: lpb[0,8192) lpl[8192,16384) FW@16384 (3200 f4)
//              BW@29184 (3136 f4) meet@41728 (256) -> 41984 floats
// ---------------------------------------------------------------------------
#define SF 48
#define SB 47

__global__ void __launch_bounds__(256) dp_kernel(float* __restrict__ out) {
    int b = blockIdx.x;
    extern __shared__ float sm[];
    float*  s_lpb  = sm;
    float*  s_lpl  = sm + 8192;
    float4* FW     = (float4*)(sm + 16384);   // rows s=0..49 (s in [1,48] used, 49 pad)
    float4* BW     = (float4*)(sm + 29184);   // rows sb=0..48 (sb in [1,47] used, 48 pad)
    float*  s_meet = sm + 41728;              // [0,64) alpha, [128,192) beta
    int tid = threadIdx.x;

    // Stage lp tables (float4, front-batched LDG).
    {
        const float4* gb = (const float4*)(g_lpb + b * TT * UU);
        const float4* gl = (const float4*)(g_lpl + b * TT * UU);
        float4* sb_ = (float4*)s_lpb;
        float4* sl_ = (float4*)s_lpl;
        float4 rb[8], rl[8];
#pragma unroll
        for (int i = 0; i < 8; i++) {
            rb[i] = __ldcg(&gb[i * 256 + tid]);
            rl[i] = __ldcg(&gl[i * 256 + tid]);
        }
#pragma unroll
        for (int i = 0; i < 8; i++) {
            sb_[i * 256 + tid] = rb[i];
            sl_[i * 256 + tid] = rl[i];
        }
    }
    __syncthreads();

    // ---- forward weights: j = s*64+u, s in [1,48] ----
    for (int j = 64 + tid; j < (SF + 1) * 64; j += 256) {
        int s = j >> 6, u = j & 63;
        int t = 2 * s - u;                     // in [-61, 96]
        int r0 = max(t, 0), r1 = max(t - 1, 0), r2 = max(t - 2, 0);
        int um1 = max(u - 1, 0), um2 = max(u - 2, 0);

        float b_r1u   = s_lpb[r1 * UU + u];
        float l_r0um1 = s_lpl[r0 * UU + um1];
        float A = s_lpb[r2 * UU + u] + b_r1u;
        float B = lae2(s_lpl[r1 * UU + um1] + b_r1u,
                       s_lpb[r1 * UU + um1] + l_r0um1);
        float C = s_lpl[r0 * UU + um2] + l_r0um1;
        if (u == 0) B = NEGF;
        if (u < 2)  C = NEGF;
        FW[j] = make_float4(A, B, C, 0.f);
    }
    // ---- backward weights: j = sb*64+u, sb in [1,47] ----
    for (int j = 64 + tid; j < (SB + 1) * 64; j += 256) {
        int sb = j >> 6, u = j & 63;
        int t = 190 - 2 * sb - u;              // >= 33 always; may be > 127
        int rt0 = min(t, TT - 1), rt1 = min(t + 1, TT - 1);
        int up1 = min(u + 1, UU - 1);

        float b00 = s_lpb[rt0 * UU + u],   b10 = s_lpb[rt1 * UU + u];
        float l00 = s_lpl[rt0 * UU + u],   l10 = s_lpl[rt1 * UU + u];
        float b01 = s_lpb[rt0 * UU + up1], l01 = s_lpl[rt0 * UU + up1];

        float A = b00 + b10;
        float B = lae2(b00 + l10, l00 + b01);
        float C = l00 + l01;
        if (u == 63) B = NEGF;
        if (u >= 62) C = NEGF;
        if (t > TT - 1) { A = NEGF; B = NEGF; C = NEGF; }  // target out-of-lattice
        BW[j] = make_float4(A, B, C, 0.f);
    }
    __syncthreads();

    int wid = tid >> 5, lane = tid & 31;
    int u_lo = lane * 2;

    if (wid == 0) {
        // ---------------- forward: 48 super-steps ----------------
        float a_lo = (lane == 0) ? 0.f : NEGF;
        float a_hi = NEGF;
        float nl_lo = __shfl_up_sync(0xffffffffu, a_lo, 1);
        float nl_hi = __shfl_up_sync(0xffffffffu, a_hi, 1);
        int W = 64 + u_lo;
        float4 w0 = FW[W], w1 = FW[W + 1];

#pragma unroll 2
        for (int s = 1; s < SF; s++) {
            float4 nw0 = FW[W + 64], nw1 = FW[W + 65];
            float n0 = lae3(a_lo + w0.x, nl_hi + w0.y, nl_lo + w0.z);
            float n1 = lae3(a_hi + w1.x, a_lo + w1.y, nl_hi + w1.z);
            a_lo = n0; a_hi = n1;
            nl_lo = __shfl_up_sync(0xffffffffu, a_lo, 1);
            nl_hi = __shfl_up_sync(0xffffffffu, a_hi, 1);
            w0 = nw0; w1 = nw1; W += 64;
        }
        // peel s = SF (no trailing shfl)
        {
            float n0 = lae3(a_lo + w0.x, nl_hi + w0.y, nl_lo + w0.z);
            float n1 = lae3(a_hi + w1.x, a_lo + w1.y, nl_hi + w1.z);
            a_lo = n0; a_hi = n1;
        }
        s_meet[u_lo]     = a_lo;
        s_meet[u_lo + 1] = a_hi;
    } else if (wid == 1) {
        // ---------------- backward: 47 super-steps ----------------
        float b_lo = NEGF;
        float b_hi = (lane == 31) ? s_lpb[(TT - 1) * UU + (UU - 1)] : NEGF;
        float nr_lo = __shfl_down_sync(0xffffffffu, b_lo, 1);
        float nr_hi = __shfl_down_sync(0xffffffffu, b_hi, 1);
        int W = 64 + u_lo;
        float4 w0 = BW[W], w1 = BW[W + 1];

#pragma unroll 2
        for (int s = 1; s < SB; s++) {
            float4 nw0 = BW[W + 64], nw1 = BW[W + 65];
            float n0 = lae3(b_lo + w0.x, b_hi + w0.y, nr_lo + w0.z);
            float n1 = lae3(b_hi + w1.x, nr_lo + w1.y, nr_hi + w1.z);
            b_lo = n0; b_hi = n1;
            nr_lo = __shfl_down_sync(0xffffffffu, b_lo, 1);
            nr_hi = __shfl_down_sync(0xffffffffu, b_hi, 1);
            w0 = nw0; w1 = nw1; W += 64;
        }
        // peel s = SB
        {
            float n0 = lae3(b_lo + w0.x, b_hi + w0.y, nr_lo + w0.z);
            float n1 = lae3(b_hi + w1.x, nr_lo + w1.y, nr_hi + w1.z);
            b_lo = n0; b_hi = n1;
        }
        s_meet[128 + u_lo]     = b_lo;
        s_meet[128 + u_lo + 1] = b_hi;
    }
    __syncthreads();

    // ---------------- combine on diag 96 + global mean ----------------
    if (wid == 0) {
        float v0 = s_meet[lane]      + s_meet[128 + lane];
        float v1 = s_meet[lane + 32] + s_meet[128 + lane + 32];
        float M = fmaxf(v0, v1);
#pragma unroll
        for (int o = 16; o; o >>= 1)
            M = fmaxf(M, __shfl_xor_sync(0xffffffffu, M, o));
        float e = fast_ex2(v0 - M) + fast_ex2(v1 - M);
#pragma unroll
        for (int o = 16; o; o >>= 1)
            e += __shfl_xor_sync(0xffffffffu, e, o);
        float ll2 = M + fast_lg2(e);           // log2-domain loglike

        int is_last = 0;
        if (lane == 0) {
            g_cost[b] = -ll2 * LN2F;
            __threadfence();
            is_last = (atomicAdd(&g_ticket, 1) == BB - 1);
        }
        is_last = __shfl_sync(0xffffffffu, is_last, 0);
        if (is_last) {
            float v = (lane < BB) ? __ldcg(&g_cost[lane]) : 0.f;
#pragma unroll
            for (int o = 16; o; o >>= 1)
                v += __shfl_xor_sync(0xffffffffu, v, o);
            if (lane == 0) {
                out[0] = v * (1.0f / BB);
                g_ticket = 0;                  // reset for next graph replay
            }
        }
    }
}

extern "C" void kernel_launch(void* const* d_in, const int* in_sizes, int n_in,
                              void* d_out, int out_size) {
    const float* acts   = (const float*)d_in[0];
    const int*   labels = (const int*)d_in[1];

    const int smem_bytes = 41984 * (int)sizeof(float);   // 167936
    cudaFuncSetAttribute(dp_kernel, cudaFuncAttributeMaxDynamicSharedMemorySize,
                         smem_bytes);

    lse_kernel<<<CELLS / 8, 256>>>(acts, labels);
    dp_kernel<<<BB, 256, smem_bytes>>>((float*)d_out);
}